// round 15
// baseline (speedup 1.0000x reference)
#include <cuda_runtime.h>
#include <math.h>
#include <float.h>

typedef unsigned long long u64;

#define B_ 8
#define T_ 4096
#define D_ 768
#define S_ 64
#define F_ 3072

// -------- scratch --------
__device__ float g_xn[B_*T_*D_];
__device__ float g_tinv[B_*T_];
__device__ float g_sl[S_*D_];
__device__ float g_logits[B_*S_*T_];   // K-partial 0 (pre-scaled by tinv)
__device__ float g_logits2[B_*S_*T_];  // K-partial 1
__device__ float g_disp[B_*S_*T_];
__device__ float g_comb[B_*S_*T_];
__device__ float g_y[B_*S_*D_];
__device__ float g_h[B_*S_*F_];        // h_pre (bias+gelu applied in ffn2 fill)
__device__ float g_y2[B_*S_*D_];

// -------- packed f32x2 helpers --------
__device__ __forceinline__ u64 ffma2(u64 a, u64 b, u64 c){
    u64 d; asm("fma.rn.f32x2 %0, %1, %2, %3;" : "=l"(d) : "l"(a), "l"(b), "l"(c)); return d;
}
__device__ __forceinline__ u64 pack2(float lo, float hi){
    u64 r; asm("mov.b64 %0, {%1, %2};" : "=l"(r) : "f"(lo), "f"(hi)); return r;
}
__device__ __forceinline__ float2 unpack2(u64 v){
    float2 r; asm("mov.b64 {%0, %1}, %2;" : "=f"(r.x), "=f"(r.y) : "l"(v)); return r;
}
__device__ __forceinline__ float gelu_f(float x){
    return 0.5f * x * (1.0f + erff(x * 0.7071067811865476f));
}

__device__ __forceinline__ float blk_sum(float v, volatile float* sbuf){
    #pragma unroll
    for (int o = 16; o; o >>= 1) v += __shfl_xor_sync(0xffffffffu, v, o);
    __syncthreads();
    if ((threadIdx.x & 31) == 0) sbuf[threadIdx.x >> 5] = v;
    __syncthreads();
    if (threadIdx.x < 32){
        int nw = blockDim.x >> 5;
        float r = (threadIdx.x < (unsigned)nw) ? sbuf[threadIdx.x] : 0.0f;
        #pragma unroll
        for (int o = 16; o; o >>= 1) r += __shfl_xor_sync(0xffffffffu, r, o);
        if (threadIdx.x == 0) sbuf[0] = r;
    }
    __syncthreads();
    return sbuf[0];
}
__device__ __forceinline__ float blk_max(float v, volatile float* sbuf){
    #pragma unroll
    for (int o = 16; o; o >>= 1) v = fmaxf(v, __shfl_xor_sync(0xffffffffu, v, o));
    __syncthreads();
    if ((threadIdx.x & 31) == 0) sbuf[threadIdx.x >> 5] = v;
    __syncthreads();
    if (threadIdx.x < 32){
        int nw = blockDim.x >> 5;
        float r = (threadIdx.x < (unsigned)nw) ? sbuf[threadIdx.x] : -FLT_MAX;
        #pragma unroll
        for (int o = 16; o; o >>= 1) r = fmaxf(r, __shfl_xor_sync(0xffffffffu, r, o));
        if (threadIdx.x == 0) sbuf[0] = r;
    }
    __syncthreads();
    return sbuf[0];
}

// K0: zero atomic accumulators
__global__ void k_zero(){
    int i = blockIdx.x * blockDim.x + threadIdx.x;   // 0..393215 float4
    float4 z = make_float4(0.f,0.f,0.f,0.f);
    ((float4*)g_h)[i] = z;
    if (i < 98304){
        ((float4*)g_y)[i]  = z;
        ((float4*)g_y2)[i] = z;
    }
}

// K1: sl = l2_normalize(slots) * scale
__global__ __launch_bounds__(256) void k_slot_prep(const float* __restrict__ slots,
                                                   const float* __restrict__ scale){
    __shared__ float sbuf[32];
    int s = blockIdx.x;
    float acc = 0.f;
    for (int d = threadIdx.x; d < D_; d += 256){ float v = slots[s*D_+d]; acc += v*v; }
    float tot = blk_sum(acc, sbuf);
    float m = scale[s] / fmaxf(sqrtf(tot), 1e-5f);
    for (int d = threadIdx.x; d < D_; d += 256) g_sl[s*D_+d] = slots[s*D_+d] * m;
}

// K2: RMSNorm + token inverse l2 norm
__global__ __launch_bounds__(256) void k_rms(const float* __restrict__ x,
                                             const float* __restrict__ w){
    __shared__ float sbuf[32];
    int row = blockIdx.x;
    const float* xr = x + (size_t)row * D_;
    float s1 = 0.f, s2 = 0.f;
    float vw[3];
    #pragma unroll
    for (int i = 0; i < 3; i++){
        int d = threadIdx.x + i*256;
        float v = xr[d];
        float t = v * w[d];
        vw[i] = t;
        s1 += v*v; s2 += t*t;
    }
    float t1 = blk_sum(s1, sbuf);
    float t2 = blk_sum(s2, sbuf);
    float rs = rsqrtf(t1 * (1.0f / D_) + 1e-5f);
    float nrm = rs * sqrtf(t2);
    if (threadIdx.x == 0) g_tinv[row] = 1.0f / fmaxf(nrm, 1e-5f);
    float* xo = g_xn + (size_t)row * D_;
    #pragma unroll
    for (int i = 0; i < 3; i++) xo[threadIdx.x + i*256] = vw[i] * rs;
}

// K3: logit partial = (sum_k sl[s][k]*xn[b][t][k]) * tinv
// 64 slots x 128 tokens, 256 thr, 8s x 4t per thread, splitK=2, k-chunk 32.
__global__ __launch_bounds__(256, 4) void k_logits(){
    int b  = blockIdx.y;
    int t0 = blockIdx.x * 128;
    int kz = blockIdx.z;
    __shared__ __align__(16) float As[32][72];
    __shared__ __align__(16) float Bs[32][132];
    int tid = threadIdx.x;
    int sg = tid >> 5;             // 8 slot groups of 8
    int tg = tid & 31;             // 32 token groups of 4

    u64 acc[8][2];
    #pragma unroll
    for (int i = 0; i < 8; i++){ acc[i][0]=0ull; acc[i][1]=0ull; }

    int k0 = kz * 384;
    // A fill: float4 f in {tid, tid+256}: slot = f>>3, kq = (f&7)<<2
    int slA = tid >> 3, kqA = (tid & 7) << 2;
    const float* aP = g_sl + slA*D_ + k0 + kqA;        // second piece: +32 slots
    // B fill: f in {tid + 256*i}: tok = (f>>3), kq same
    const float* bP = g_xn + (size_t)(b*T_ + t0 + slA)*D_ + k0 + kqA;  // tok0 = slA (0..31)

    for (int kb = 0; kb < 384; kb += 32){
        float4 ra0 = *(const float4*)(aP + kb);
        float4 ra1 = *(const float4*)(aP + (size_t)32*D_ + kb);
        float4 rb0 = *(const float4*)(bP + kb);
        float4 rb1 = *(const float4*)(bP + (size_t)32*D_ + kb);
        float4 rb2 = *(const float4*)(bP + (size_t)64*D_ + kb);
        float4 rb3 = *(const float4*)(bP + (size_t)96*D_ + kb);
        if (kb) __syncthreads();
        As[kqA+0][slA]=ra0.x; As[kqA+1][slA]=ra0.y; As[kqA+2][slA]=ra0.z; As[kqA+3][slA]=ra0.w;
        As[kqA+0][slA+32]=ra1.x; As[kqA+1][slA+32]=ra1.y; As[kqA+2][slA+32]=ra1.z; As[kqA+3][slA+32]=ra1.w;
        Bs[kqA+0][slA]=rb0.x; Bs[kqA+1][slA]=rb0.y; Bs[kqA+2][slA]=rb0.z; Bs[kqA+3][slA]=rb0.w;
        Bs[kqA+0][slA+32]=rb1.x; Bs[kqA+1][slA+32]=rb1.y; Bs[kqA+2][slA+32]=rb1.z; Bs[kqA+3][slA+32]=rb1.w;
        Bs[kqA+0][slA+64]=rb2.x; Bs[kqA+1][slA+64]=rb2.y; Bs[kqA+2][slA+64]=rb2.z; Bs[kqA+3][slA+64]=rb2.w;
        Bs[kqA+0][slA+96]=rb3.x; Bs[kqA+1][slA+96]=rb3.y; Bs[kqA+2][slA+96]=rb3.z; Bs[kqA+3][slA+96]=rb3.w;
        __syncthreads();
        #pragma unroll 8
        for (int k = 0; k < 32; k++){
            ulonglong2 ta = *(const ulonglong2*)&Bs[k][tg*4];
            {
                float4 s0 = *(const float4*)&As[k][sg*8];
                u64 c0=pack2(s0.x,s0.x), c1=pack2(s0.y,s0.y), c2=pack2(s0.z,s0.z), c3=pack2(s0.w,s0.w);
                acc[0][0]=ffma2(ta.x,c0,acc[0][0]); acc[0][1]=ffma2(ta.y,c0,acc[0][1]);
                acc[1][0]=ffma2(ta.x,c1,acc[1][0]); acc[1][1]=ffma2(ta.y,c1,acc[1][1]);
                acc[2][0]=ffma2(ta.x,c2,acc[2][0]); acc[2][1]=ffma2(ta.y,c2,acc[2][1]);
                acc[3][0]=ffma2(ta.x,c3,acc[3][0]); acc[3][1]=ffma2(ta.y,c3,acc[3][1]);
            }
            {
                float4 s1 = *(const float4*)&As[k][sg*8 + 4];
                u64 c4=pack2(s1.x,s1.x), c5=pack2(s1.y,s1.y), c6=pack2(s1.z,s1.z), c7=pack2(s1.w,s1.w);
                acc[4][0]=ffma2(ta.x,c4,acc[4][0]); acc[4][1]=ffma2(ta.y,c4,acc[4][1]);
                acc[5][0]=ffma2(ta.x,c5,acc[5][0]); acc[5][1]=ffma2(ta.y,c5,acc[5][1]);
                acc[6][0]=ffma2(ta.x,c6,acc[6][0]); acc[6][1]=ffma2(ta.y,c6,acc[6][1]);
                acc[7][0]=ffma2(ta.x,c7,acc[7][0]); acc[7][1]=ffma2(ta.y,c7,acc[7][1]);
            }
        }
    }
    float tv0 = g_tinv[b*T_ + t0 + tg*4 + 0];
    float tv1 = g_tinv[b*T_ + t0 + tg*4 + 1];
    float tv2 = g_tinv[b*T_ + t0 + tg*4 + 2];
    float tv3 = g_tinv[b*T_ + t0 + tg*4 + 3];
    float* dst = kz ? g_logits2 : g_logits;
    #pragma unroll
    for (int si = 0; si < 8; si++){
        int s = sg*8 + si;
        float2 p0 = unpack2(acc[si][0]);
        float2 p1 = unpack2(acc[si][1]);
        *(float4*)(dst + (size_t)(b*S_ + s)*T_ + t0 + tg*4) =
            make_float4(p0.x*tv0, p0.y*tv1, p1.x*tv2, p1.y*tv3);
    }
}

// K4: dispatch softmax over T per (b,s)
__global__ __launch_bounds__(256) void k_disp_soft(){
    __shared__ float sm[T_];
    __shared__ float sbuf[32];
    int s = blockIdx.x, b = blockIdx.y;
    size_t off = (size_t)(b*S_ + s) * T_;
    const float* r0 = g_logits + off;
    const float* r1 = g_logits2 + off;
    float mx = -FLT_MAX;
    for (int i = threadIdx.x; i < T_; i += 256){
        float l = r0[i] + r1[i];
        sm[i] = l;
        mx = fmaxf(mx, l);
    }
    mx = blk_max(mx, sbuf);
    float sum = 0.f;
    for (int i = threadIdx.x; i < T_; i += 256){
        float e = expf(sm[i] - mx); sm[i] = e; sum += e;
    }
    sum = blk_sum(sum, sbuf);
    float inv = 1.0f / sum;
    float* o = g_disp + off;
    for (int i = threadIdx.x; i < T_; i += 256) o[i] = sm[i] * inv;
}

// K5: combine softmax over S per (b,t)
__global__ __launch_bounds__(128) void k_comb_soft(){
    int b = blockIdx.y;
    int t = blockIdx.x * 128 + threadIdx.x;
    float v[S_];
    float mx = -FLT_MAX;
    #pragma unroll
    for (int s = 0; s < S_; s++){
        size_t ix = (size_t)(b*S_+s)*T_ + t;
        v[s] = g_logits[ix] + g_logits2[ix];
        mx = fmaxf(mx, v[s]);
    }
    float sum = 0.f;
    #pragma unroll
    for (int s = 0; s < S_; s++){ v[s] = expf(v[s] - mx); sum += v[s]; }
    float inv = 1.0f / sum;
    #pragma unroll
    for (int s = 0; s < S_; s++) g_comb[(size_t)(b*S_+s)*T_ + t] = v[s] * inv;
}

// K6: y[b][s][d] = sum_t disp[b][s][t]*xn[b][t][d]
// 64 slots x 128 d, 256 thr, 8s x 4d per thread, splitT=8, k-chunk 32.
__global__ __launch_bounds__(256, 4) void k_dispatch(){
    int b   = blockIdx.y;
    int d0  = blockIdx.x * 128;
    int tz0 = blockIdx.z * 512;
    __shared__ __align__(16) float As[32][72];    // disp [k][slot]
    __shared__ __align__(16) float Bs[32][132];   // xn   [k][d]
    int tid = threadIdx.x;
    int sg = tid >> 5;
    int dg = tid & 31;

    u64 acc[8][2];
    #pragma unroll
    for (int i = 0; i < 8; i++){ acc[i][0]=0ull; acc[i][1]=0ull; }

    // A fill: f in {tid, tid+256}: slot = f>>3, kq = (f&7)<<2
    int slA = tid >> 3, kqA = (tid & 7) << 2;
    const float* aP = g_disp + (size_t)(b*S_ + slA)*T_ + tz0 + kqA;   // +32 slots second
    // B fill: f in {tid+256i}: k = f>>5 (row of 32 f4), dq = (f&31)<<2
    int krB = tid >> 5, dqB = (tid & 31) << 2;
    const float* bP = g_xn + (size_t)(b*T_ + tz0 + krB)*D_ + d0 + dqB; // +8 k per piece

    for (int kb = 0; kb < 512; kb += 32){
        float4 ra0 = *(const float4*)(aP + kb);
        float4 ra1 = *(const float4*)(aP + (size_t)32*T_ + kb);
        float4 rb0 = *(const float4*)(bP + (size_t)(kb+ 0)*D_);
        float4 rb1 = *(const float4*)(bP + (size_t)(kb+ 8)*D_);
        float4 rb2 = *(const float4*)(bP + (size_t)(kb+16)*D_);
        float4 rb3 = *(const float4*)(bP + (size_t)(kb+24)*D_);
        if (kb) __syncthreads();
        As[kqA+0][slA]=ra0.x; As[kqA+1][slA]=ra0.y; As[kqA+2][slA]=ra0.z; As[kqA+3][slA]=ra0.w;
        As[kqA+0][slA+32]=ra1.x; As[kqA+1][slA+32]=ra1.y; As[kqA+2][slA+32]=ra1.z; As[kqA+3][slA+32]=ra1.w;
        *(float4*)&Bs[krB   ][dqB] = rb0;
        *(float4*)&Bs[krB+ 8][dqB] = rb1;
        *(float4*)&Bs[krB+16][dqB] = rb2;
        *(float4*)&Bs[krB+24][dqB] = rb3;
        __syncthreads();
        #pragma unroll 8
        for (int k = 0; k < 32; k++){
            ulonglong2 da = *(const ulonglong2*)&Bs[k][dg*4];
            {
                float4 s0 = *(const float4*)&As[k][sg*8];
                u64 c0=pack2(s0.x,s0.x), c1=pack2(s0.y,s0.y), c2=pack2(s0.z,s0.z), c3=pack2(s0.w,s0.w);
                acc[0][0]=ffma2(da.x,c0,acc[0][0]); acc[0][1]=ffma2(da.y,c0,acc[0][1]);
                acc[1][0]=ffma2(da.x,c1,acc[1][0]); acc[1][1]=ffma2(da.y,c1,acc[1][1]);
                acc[2][0]=ffma2(da.x,c2,acc[2][0]); acc[2][1]=ffma2(da.y,c2,acc[2][1]);
                acc[3][0]=ffma2(da.x,c3,acc[3][0]); acc[3][1]=ffma2(da.y,c3,acc[3][1]);
            }
            {
                float4 s1 = *(const float4*)&As[k][sg*8 + 4];
                u64 c4=pack2(s1.x,s1.x), c5=pack2(s1.y,s1.y), c6=pack2(s1.z,s1.z), c7=pack2(s1.w,s1.w);
                acc[4][0]=ffma2(da.x,c4,acc[4][0]); acc[4][1]=ffma2(da.y,c4,acc[4][1]);
                acc[5][0]=ffma2(da.x,c5,acc[5][0]); acc[5][1]=ffma2(da.y,c5,acc[5][1]);
                acc[6][0]=ffma2(da.x,c6,acc[6][0]); acc[6][1]=ffma2(da.y,c6,acc[6][1]);
                acc[7][0]=ffma2(da.x,c7,acc[7][0]); acc[7][1]=ffma2(da.y,c7,acc[7][1]);
            }
        }
    }
    #pragma unroll
    for (int si = 0; si < 8; si++){
        int s = sg*8 + si;
        float* dst = &g_y[(size_t)(b*S_ + s)*D_ + d0 + dg*4];
        float2 p0 = unpack2(acc[si][0]);
        float2 p1 = unpack2(acc[si][1]);
        atomicAdd(dst+0, p0.x);
        atomicAdd(dst+1, p0.y);
        atomicAdd(dst+2, p1.x);
        atomicAdd(dst+3, p1.y);
    }
}

// K7: h_pre += sum_{d chunk} y*W1   (splitD=4, atomics). 256 thr, 4 f per thread.
__global__ __launch_bounds__(256) void k_ffn1a(const float* __restrict__ W1){
    int s  = blockIdx.y;
    int dz = blockIdx.z;
    int f0 = blockIdx.x * 1024 + threadIdx.x * 4;
    __shared__ __align__(16) u64 ys2[8][192];
    #pragma unroll
    for (int it = 0; it < 6; it++){
        int i = it*256 + threadIdx.x;     // 0..1535
        int bb = i / 192, d = i - bb*192;
        float v = g_y[(size_t)(bb*S_ + s)*D_ + dz*192 + d];
        ys2[bb][d] = pack2(v, v);
    }
    __syncthreads();

    u64 acc[8][2];
    #pragma unroll
    for (int bb = 0; bb < 8; bb++){ acc[bb][0]=0ull; acc[bb][1]=0ull; }

    const float* wbase = W1 + ((size_t)s*D_ + dz*192)*F_ + f0;
    #pragma unroll 4
    for (int d0 = 0; d0 < 192; d0 += 2){
        const float* wp = wbase + (size_t)d0 * F_;
        ulonglong2 w0 = *(const ulonglong2*)(wp);
        ulonglong2 w1 = *(const ulonglong2*)(wp + F_);
        #pragma unroll
        for (int bb = 0; bb < 8; bb++){
            ulonglong2 yp = *(const ulonglong2*)&ys2[bb][d0];
            acc[bb][0]=ffma2(w0.x, yp.x, acc[bb][0]);
            acc[bb][1]=ffma2(w0.y, yp.x, acc[bb][1]);
            acc[bb][0]=ffma2(w1.x, yp.y, acc[bb][0]);
            acc[bb][1]=ffma2(w1.y, yp.y, acc[bb][1]);
        }
    }
    #pragma unroll
    for (int bb = 0; bb < 8; bb++){
        float* dst = &g_h[(size_t)(bb*S_ + s)*F_ + f0];
        float2 p0 = unpack2(acc[bb][0]);
        float2 p1 = unpack2(acc[bb][1]);
        atomicAdd(dst+0, p0.x);
        atomicAdd(dst+1, p0.y);
        atomicAdd(dst+2, p1.x);
        atomicAdd(dst+3, p1.y);
    }
}

// K8: y2 += sum_{f chunk} gelu(h_pre+b1)*W2  (splitF=8, atomics). 192 thr, 4 d per thread.
__global__ __launch_bounds__(192) void k_ffn2(const float* __restrict__ W2,
                                              const float* __restrict__ b1){
    int s  = blockIdx.x;
    int fz = blockIdx.y;
    int d0 = threadIdx.x * 4;
    __shared__ __align__(16) u64 hs2[8][384];
    #pragma unroll
    for (int it = 0; it < 16; it++){
        int i = it*192 + threadIdx.x;      // 0..3071
        int bb = i / 384, f = i - bb*384;
        float v = g_h[(size_t)(bb*S_ + s)*F_ + fz*384 + f];
        v = gelu_f(v + b1[s*F_ + fz*384 + f]);
        hs2[bb][f] = pack2(v, v);
    }
    __syncthreads();

    u64 acc[8][2];
    #pragma unroll
    for (int bb = 0; bb < 8; bb++){ acc[bb][0]=0ull; acc[bb][1]=0ull; }

    const float* wbase = W2 + ((size_t)s*F_ + fz*384)*D_ + d0;
    #pragma unroll 4
    for (int f0 = 0; f0 < 384; f0 += 2){
        const float* wp = wbase + (size_t)f0 * D_;
        ulonglong2 w0 = *(const ulonglong2*)(wp);
        ulonglong2 w1 = *(const ulonglong2*)(wp + D_);
        #pragma unroll
        for (int bb = 0; bb < 8; bb++){
            ulonglong2 hp = *(const ulonglong2*)&hs2[bb][f0];
            acc[bb][0]=ffma2(w0.x, hp.x, acc[bb][0]);
            acc[bb][1]=ffma2(w0.y, hp.x, acc[bb][1]);
            acc[bb][0]=ffma2(w1.x, hp.y, acc[bb][0]);
            acc[bb][1]=ffma2(w1.y, hp.y, acc[bb][1]);
        }
    }
    #pragma unroll
    for (int bb = 0; bb < 8; bb++){
        float* dst = &g_y2[(size_t)(bb*S_ + s)*D_ + d0];
        float2 p0 = unpack2(acc[bb][0]);
        float2 p1 = unpack2(acc[bb][1]);
        atomicAdd(dst+0, p0.x);
        atomicAdd(dst+1, p0.y);
        atomicAdd(dst+2, p1.x);
        atomicAdd(dst+3, p1.y);
    }
}

// K9: out[b][t][d] = sum_s (y2+b2)*comb. 64t x 128d, 256 thr, 8t x 4d per thread.
#define FINAL_SMEM (64*72*4 + 64*136*4)
__global__ __launch_bounds__(256) void k_final(const float* __restrict__ b2,
                                               float* __restrict__ out){
    extern __shared__ __align__(16) char smraw[];
    float* Cs = (float*)smraw;                 // [64][72]   comb [s][t]
    float* Ys = (float*)(smraw + 64*72*4);     // [64][136]  y2+bias [s][d]
    int t0 = blockIdx.x * 64;
    int dt = blockIdx.y * 128;
    int b  = blockIdx.z;
    int tid = threadIdx.x;
    int tg = tid >> 5;    // 8 t-groups of 8
    int dg = tid & 31;    // 32 d-groups of 4

    #pragma unroll
    for (int it = 0; it < 8; it++){
        int i = it*256 + tid;              // 0..2047
        int s = i >> 5, dq = (i & 31) << 2;
        float4 yv = *(const float4*)&g_y2[(size_t)(b*S_ + s)*D_ + dt + dq];
        float4 bv = *(const float4*)&b2[s*D_ + dt + dq];
        yv.x += bv.x; yv.y += bv.y; yv.z += bv.z; yv.w += bv.w;
        *(float4*)&Ys[s*136 + dq] = yv;
    }
    #pragma unroll
    for (int it = 0; it < 4; it++){
        int i = it*256 + tid;              // 0..1023
        int s = i >> 4, tq = (i & 15) << 2;
        *(float4*)&Cs[s*72 + tq] = *(const float4*)&g_comb[(size_t)(b*S_ + s)*T_ + t0 + tq];
    }
    __syncthreads();

    u64 acc[8][2];
    #pragma unroll
    for (int i = 0; i < 8; i++){ acc[i][0]=0ull; acc[i][1]=0ull; }

    #pragma unroll 4
    for (int s = 0; s < S_; s++){
        float4 c0 = *(const float4*)&Cs[s*72 + tg*8];
        float4 c1 = *(const float4*)&Cs[s*72 + tg*8 + 4];
        ulonglong2 ya = *(const ulonglong2*)&Ys[s*136 + dg*4];
        u64 cc[8];
        cc[0]=pack2(c0.x,c0.x); cc[1]=pack2(c0.y,c0.y); cc[2]=pack2(c0.z,c0.z); cc[3]=pack2(c0.w,c0.w);
        cc[4]=pack2(c1.x,c1.x); cc[5]=pack2(c1.y,c1.y); cc[6]=pack2(c1.z,c1.z); cc[7]=pack2(c1.w,c1.w);
        #pragma unroll
        for (int ti = 0; ti < 8; ti++){
            acc[ti][0]=ffma2(ya.x, cc[ti], acc[ti][0]);
            acc[ti][1]=ffma2(ya.y, cc[ti], acc[ti][1]);
        }
    }

    #pragma unroll
    for (int ti = 0; ti < 8; ti++){
        int t = t0 + tg*8 + ti;
        float2 p0 = unpack2(acc[ti][0]);
        float2 p1 = unpack2(acc[ti][1]);
        *(float4*)(out + (size_t)(b*T_ + t)*D_ + dt + dg*4) =
            make_float4(p0.x, p0.y, p1.x, p1.y);
    }
}

// -------- launch --------
extern "C" void kernel_launch(void* const* d_in, const int* in_sizes, int n_in,
                              void* d_out, int out_size){
    const float* x     = (const float*)d_in[0];
    const float* slots = (const float*)d_in[1];
    const float* scale = (const float*)d_in[2];
    const float* fc1_w = (const float*)d_in[3];
    const float* fc1_b = (const float*)d_in[4];
    const float* fc2_w = (const float*)d_in[5];
    const float* fc2_b = (const float*)d_in[6];
    const float* nw    = (const float*)d_in[7];
    float* out = (float*)d_out;

    cudaFuncSetAttribute(k_final, cudaFuncAttributeMaxDynamicSharedMemorySize, FINAL_SMEM);

    k_zero<<<1536, 256>>>();
    k_slot_prep<<<S_, 256>>>(slots, scale);
    k_rms<<<B_*T_, 256>>>(x, nw);
    k_logits<<<dim3(T_/128, B_, 2), 256>>>();
    k_disp_soft<<<dim3(S_, B_), 256>>>();
    k_comb_soft<<<dim3(T_/128, B_), 128>>>();
    k_dispatch<<<dim3(D_/128, B_, 8), 256>>>();
    k_ffn1a<<<dim3(F_/1024, S_, 4), 256>>>(fc1_w);
    k_ffn2<<<dim3(S_, 8), 192>>>(fc2_w, fc1_b);
    k_final<<<dim3(T_/64, D_/128, B_), 256, FINAL_SMEM>>>(fc2_b, out);
}

// round 16
// speedup vs baseline: 1.0417x; 1.0417x over previous
#include <cuda_runtime.h>
#include <math.h>
#include <float.h>

typedef unsigned long long u64;

#define B_ 8
#define T_ 4096
#define D_ 768
#define S_ 64
#define F_ 3072

// -------- scratch --------
__device__ float g_xn[B_*T_*D_];
__device__ float g_tinv[B_*T_];
__device__ float g_sl[S_*D_];
__device__ float g_logits[B_*S_*T_];   // K-partial 0 (pre-scaled by tinv)
__device__ float g_logits2[B_*S_*T_];  // K-partial 1
__device__ float g_disp[B_*S_*T_];
__device__ float g_comb[B_*S_*T_];
__device__ float g_y[B_*S_*D_];
__device__ float g_h[B_*S_*F_];        // h_pre (bias+gelu applied in ffn2 fill)
__device__ float g_y2[B_*S_*D_];

// -------- packed f32x2 helpers --------
__device__ __forceinline__ u64 ffma2(u64 a, u64 b, u64 c){
    u64 d; asm("fma.rn.f32x2 %0, %1, %2, %3;" : "=l"(d) : "l"(a), "l"(b), "l"(c)); return d;
}
__device__ __forceinline__ u64 pack2(float lo, float hi){
    u64 r; asm("mov.b64 %0, {%1, %2};" : "=l"(r) : "f"(lo), "f"(hi)); return r;
}
__device__ __forceinline__ float2 unpack2(u64 v){
    float2 r; asm("mov.b64 {%0, %1}, %2;" : "=f"(r.x), "=f"(r.y) : "l"(v)); return r;
}
__device__ __forceinline__ float gelu_f(float x){
    return 0.5f * x * (1.0f + erff(x * 0.7071067811865476f));
}

__device__ __forceinline__ float blk_sum(float v, volatile float* sbuf){
    #pragma unroll
    for (int o = 16; o; o >>= 1) v += __shfl_xor_sync(0xffffffffu, v, o);
    __syncthreads();
    if ((threadIdx.x & 31) == 0) sbuf[threadIdx.x >> 5] = v;
    __syncthreads();
    if (threadIdx.x < 32){
        int nw = blockDim.x >> 5;
        float r = (threadIdx.x < (unsigned)nw) ? sbuf[threadIdx.x] : 0.0f;
        #pragma unroll
        for (int o = 16; o; o >>= 1) r += __shfl_xor_sync(0xffffffffu, r, o);
        if (threadIdx.x == 0) sbuf[0] = r;
    }
    __syncthreads();
    return sbuf[0];
}
__device__ __forceinline__ float blk_max(float v, volatile float* sbuf){
    #pragma unroll
    for (int o = 16; o; o >>= 1) v = fmaxf(v, __shfl_xor_sync(0xffffffffu, v, o));
    __syncthreads();
    if ((threadIdx.x & 31) == 0) sbuf[threadIdx.x >> 5] = v;
    __syncthreads();
    if (threadIdx.x < 32){
        int nw = blockDim.x >> 5;
        float r = (threadIdx.x < (unsigned)nw) ? sbuf[threadIdx.x] : -FLT_MAX;
        #pragma unroll
        for (int o = 16; o; o >>= 1) r = fmaxf(r, __shfl_xor_sync(0xffffffffu, r, o));
        if (threadIdx.x == 0) sbuf[0] = r;
    }
    __syncthreads();
    return sbuf[0];
}

// K0: zero atomic accumulators
__global__ void k_zero(){
    int i = blockIdx.x * blockDim.x + threadIdx.x;   // 0..393215 float4
    float4 z = make_float4(0.f,0.f,0.f,0.f);
    ((float4*)g_h)[i] = z;
    if (i < 98304){
        ((float4*)g_y)[i]  = z;
        ((float4*)g_y2)[i] = z;
    }
}

// K1: sl = l2_normalize(slots) * scale
__global__ __launch_bounds__(256) void k_slot_prep(const float* __restrict__ slots,
                                                   const float* __restrict__ scale){
    __shared__ float sbuf[32];
    int s = blockIdx.x;
    float acc = 0.f;
    for (int d = threadIdx.x; d < D_; d += 256){ float v = slots[s*D_+d]; acc += v*v; }
    float tot = blk_sum(acc, sbuf);
    float m = scale[s] / fmaxf(sqrtf(tot), 1e-5f);
    for (int d = threadIdx.x; d < D_; d += 256) g_sl[s*D_+d] = slots[s*D_+d] * m;
}

// K2: RMSNorm + token inverse l2 norm
__global__ __launch_bounds__(256) void k_rms(const float* __restrict__ x,
                                             const float* __restrict__ w){
    __shared__ float sbuf[32];
    int row = blockIdx.x;
    const float* xr = x + (size_t)row * D_;
    float s1 = 0.f, s2 = 0.f;
    float vw[3];
    #pragma unroll
    for (int i = 0; i < 3; i++){
        int d = threadIdx.x + i*256;
        float v = xr[d];
        float t = v * w[d];
        vw[i] = t;
        s1 += v*v; s2 += t*t;
    }
    float t1 = blk_sum(s1, sbuf);
    float t2 = blk_sum(s2, sbuf);
    float rs = rsqrtf(t1 * (1.0f / D_) + 1e-5f);
    float nrm = rs * sqrtf(t2);
    if (threadIdx.x == 0) g_tinv[row] = 1.0f / fmaxf(nrm, 1e-5f);
    float* xo = g_xn + (size_t)row * D_;
    #pragma unroll
    for (int i = 0; i < 3; i++) xo[threadIdx.x + i*256] = vw[i] * rs;
}

// K3: logit partial = (sum_k sl[s][k]*xn[b][t][k]) * tinv
// 64 slots x 128 tokens, 256 thr, 8s x 4t per thread, splitK=2, k-chunk 16. (R14 best)
__global__ __launch_bounds__(256, 4) void k_logits(){
    int b  = blockIdx.y;
    int t0 = blockIdx.x * 128;
    int kz = blockIdx.z;
    __shared__ __align__(16) float As[16][72];
    __shared__ __align__(16) float Bs[16][132];
    int tid = threadIdx.x;
    int sg = tid >> 5;             // 8 slot groups of 8
    int tg = tid & 31;             // 32 token groups of 4

    u64 acc[8][2];
    #pragma unroll
    for (int i = 0; i < 8; i++){ acc[i][0]=0ull; acc[i][1]=0ull; }

    int k0 = kz * 384;
    int slA = tid >> 2, kqA = (tid & 3) << 2;
    const float* aP  = g_sl + slA*D_ + k0 + kqA;
    int tok0 = tid >> 2, kqB = (tid & 3) << 2;
    const float* bP0 = g_xn + (size_t)(b*T_ + t0 + tok0)*D_ + k0 + kqB;
    const float* bP1 = bP0 + (size_t)64*D_;

    for (int kb = 0; kb < 384; kb += 16){
        float4 ra  = *(const float4*)(aP  + kb);
        float4 rb0 = *(const float4*)(bP0 + kb);
        float4 rb1 = *(const float4*)(bP1 + kb);
        if (kb) __syncthreads();
        As[kqA+0][slA]=ra.x; As[kqA+1][slA]=ra.y; As[kqA+2][slA]=ra.z; As[kqA+3][slA]=ra.w;
        Bs[kqB+0][tok0]=rb0.x; Bs[kqB+1][tok0]=rb0.y; Bs[kqB+2][tok0]=rb0.z; Bs[kqB+3][tok0]=rb0.w;
        Bs[kqB+0][tok0+64]=rb1.x; Bs[kqB+1][tok0+64]=rb1.y; Bs[kqB+2][tok0+64]=rb1.z; Bs[kqB+3][tok0+64]=rb1.w;
        __syncthreads();
        #pragma unroll
        for (int k = 0; k < 16; k++){
            ulonglong2 ta = *(const ulonglong2*)&Bs[k][tg*4];
            {
                float4 s0 = *(const float4*)&As[k][sg*8];
                u64 c0=pack2(s0.x,s0.x), c1=pack2(s0.y,s0.y), c2=pack2(s0.z,s0.z), c3=pack2(s0.w,s0.w);
                acc[0][0]=ffma2(ta.x,c0,acc[0][0]); acc[0][1]=ffma2(ta.y,c0,acc[0][1]);
                acc[1][0]=ffma2(ta.x,c1,acc[1][0]); acc[1][1]=ffma2(ta.y,c1,acc[1][1]);
                acc[2][0]=ffma2(ta.x,c2,acc[2][0]); acc[2][1]=ffma2(ta.y,c2,acc[2][1]);
                acc[3][0]=ffma2(ta.x,c3,acc[3][0]); acc[3][1]=ffma2(ta.y,c3,acc[3][1]);
            }
            {
                float4 s1 = *(const float4*)&As[k][sg*8 + 4];
                u64 c4=pack2(s1.x,s1.x), c5=pack2(s1.y,s1.y), c6=pack2(s1.z,s1.z), c7=pack2(s1.w,s1.w);
                acc[4][0]=ffma2(ta.x,c4,acc[4][0]); acc[4][1]=ffma2(ta.y,c4,acc[4][1]);
                acc[5][0]=ffma2(ta.x,c5,acc[5][0]); acc[5][1]=ffma2(ta.y,c5,acc[5][1]);
                acc[6][0]=ffma2(ta.x,c6,acc[6][0]); acc[6][1]=ffma2(ta.y,c6,acc[6][1]);
                acc[7][0]=ffma2(ta.x,c7,acc[7][0]); acc[7][1]=ffma2(ta.y,c7,acc[7][1]);
            }
        }
    }
    float tv0 = g_tinv[b*T_ + t0 + tg*4 + 0];
    float tv1 = g_tinv[b*T_ + t0 + tg*4 + 1];
    float tv2 = g_tinv[b*T_ + t0 + tg*4 + 2];
    float tv3 = g_tinv[b*T_ + t0 + tg*4 + 3];
    float* dst = kz ? g_logits2 : g_logits;
    #pragma unroll
    for (int si = 0; si < 8; si++){
        int s = sg*8 + si;
        float2 p0 = unpack2(acc[si][0]);
        float2 p1 = unpack2(acc[si][1]);
        *(float4*)(dst + (size_t)(b*S_ + s)*T_ + t0 + tg*4) =
            make_float4(p0.x*tv0, p0.y*tv1, p1.x*tv2, p1.y*tv3);
    }
}

// K4: dispatch softmax over T per (b,s)
__global__ __launch_bounds__(256) void k_disp_soft(){
    __shared__ float sm[T_];
    __shared__ float sbuf[32];
    int s = blockIdx.x, b = blockIdx.y;
    size_t off = (size_t)(b*S_ + s) * T_;
    const float* r0 = g_logits + off;
    const float* r1 = g_logits2 + off;
    float mx = -FLT_MAX;
    for (int i = threadIdx.x; i < T_; i += 256){
        float l = r0[i] + r1[i];
        sm[i] = l;
        mx = fmaxf(mx, l);
    }
    mx = blk_max(mx, sbuf);
    float sum = 0.f;
    for (int i = threadIdx.x; i < T_; i += 256){
        float e = expf(sm[i] - mx); sm[i] = e; sum += e;
    }
    sum = blk_sum(sum, sbuf);
    float inv = 1.0f / sum;
    float* o = g_disp + off;
    for (int i = threadIdx.x; i < T_; i += 256) o[i] = sm[i] * inv;
}

// K5: combine softmax over S per (b,t)
__global__ __launch_bounds__(128) void k_comb_soft(){
    int b = blockIdx.y;
    int t = blockIdx.x * 128 + threadIdx.x;
    float v[S_];
    float mx = -FLT_MAX;
    #pragma unroll
    for (int s = 0; s < S_; s++){
        size_t ix = (size_t)(b*S_+s)*T_ + t;
        v[s] = g_logits[ix] + g_logits2[ix];
        mx = fmaxf(mx, v[s]);
    }
    float sum = 0.f;
    #pragma unroll
    for (int s = 0; s < S_; s++){ v[s] = expf(v[s] - mx); sum += v[s]; }
    float inv = 1.0f / sum;
    #pragma unroll
    for (int s = 0; s < S_; s++) g_comb[(size_t)(b*S_+s)*T_ + t] = v[s] * inv;
}

// K6: y[b][s][d] = sum_t disp[b][s][t]*xn[b][t][d]
// 64 slots x 128 d, 256 thr, 8s x 4d per thread, splitT=8, k-chunk 16. (R14 best)
__global__ __launch_bounds__(256, 4) void k_dispatch(){
    int b   = blockIdx.y;
    int d0  = blockIdx.x * 128;
    int tz0 = blockIdx.z * 512;
    __shared__ __align__(16) float As[16][72];    // disp [k][slot]
    __shared__ __align__(16) float Bs[16][132];   // xn   [k][d]
    int tid = threadIdx.x;
    int sg = tid >> 5;
    int dg = tid & 31;

    u64 acc[8][2];
    #pragma unroll
    for (int i = 0; i < 8; i++){ acc[i][0]=0ull; acc[i][1]=0ull; }

    int slA = tid >> 2, kqA = (tid & 3) << 2;
    const float* aP = g_disp + (size_t)(b*S_ + slA)*T_ + tz0 + kqA;
    int kr0 = tid >> 5, dqB = (tid & 31) << 2;
    const float* bP0 = g_xn + (size_t)(b*T_ + tz0 + kr0)*D_ + d0 + dqB;
    const float* bP1 = bP0 + (size_t)8*D_;

    for (int kb = 0; kb < 512; kb += 16){
        float4 ra  = *(const float4*)(aP + kb);
        float4 rb0 = *(const float4*)(bP0 + (size_t)kb*D_);
        float4 rb1 = *(const float4*)(bP1 + (size_t)kb*D_);
        if (kb) __syncthreads();
        As[kqA+0][slA]=ra.x; As[kqA+1][slA]=ra.y; As[kqA+2][slA]=ra.z; As[kqA+3][slA]=ra.w;
        *(float4*)&Bs[kr0][dqB]   = rb0;
        *(float4*)&Bs[kr0+8][dqB] = rb1;
        __syncthreads();
        #pragma unroll
        for (int k = 0; k < 16; k++){
            ulonglong2 da = *(const ulonglong2*)&Bs[k][dg*4];
            {
                float4 s0 = *(const float4*)&As[k][sg*8];
                u64 c0=pack2(s0.x,s0.x), c1=pack2(s0.y,s0.y), c2=pack2(s0.z,s0.z), c3=pack2(s0.w,s0.w);
                acc[0][0]=ffma2(da.x,c0,acc[0][0]); acc[0][1]=ffma2(da.y,c0,acc[0][1]);
                acc[1][0]=ffma2(da.x,c1,acc[1][0]); acc[1][1]=ffma2(da.y,c1,acc[1][1]);
                acc[2][0]=ffma2(da.x,c2,acc[2][0]); acc[2][1]=ffma2(da.y,c2,acc[2][1]);
                acc[3][0]=ffma2(da.x,c3,acc[3][0]); acc[3][1]=ffma2(da.y,c3,acc[3][1]);
            }
            {
                float4 s1 = *(const float4*)&As[k][sg*8 + 4];
                u64 c4=pack2(s1.x,s1.x), c5=pack2(s1.y,s1.y), c6=pack2(s1.z,s1.z), c7=pack2(s1.w,s1.w);
                acc[4][0]=ffma2(da.x,c4,acc[4][0]); acc[4][1]=ffma2(da.y,c4,acc[4][1]);
                acc[5][0]=ffma2(da.x,c5,acc[5][0]); acc[5][1]=ffma2(da.y,c5,acc[5][1]);
                acc[6][0]=ffma2(da.x,c6,acc[6][0]); acc[6][1]=ffma2(da.y,c6,acc[6][1]);
                acc[7][0]=ffma2(da.x,c7,acc[7][0]); acc[7][1]=ffma2(da.y,c7,acc[7][1]);
            }
        }
    }
    #pragma unroll
    for (int si = 0; si < 8; si++){
        int s = sg*8 + si;
        float* dst = &g_y[(size_t)(b*S_ + s)*D_ + d0 + dg*4];
        float2 p0 = unpack2(acc[si][0]);
        float2 p1 = unpack2(acc[si][1]);
        atomicAdd(dst+0, p0.x);
        atomicAdd(dst+1, p0.y);
        atomicAdd(dst+2, p1.x);
        atomicAdd(dst+3, p1.y);
    }
}

// K7: h_pre += sum_{d chunk} y*W1   (splitD=2, atomics). 256 thr, 4 f per thread.
__global__ __launch_bounds__(256) void k_ffn1a(const float* __restrict__ W1){
    int s  = blockIdx.y;
    int dz = blockIdx.z;
    int f0 = blockIdx.x * 1024 + threadIdx.x * 4;
    __shared__ __align__(16) u64 ys2[8][384];
    #pragma unroll
    for (int it = 0; it < 12; it++){
        int i = it*256 + threadIdx.x;     // 0..3071
        int bb = i / 384, d = i - bb*384;
        float v = g_y[(size_t)(bb*S_ + s)*D_ + dz*384 + d];
        ys2[bb][d] = pack2(v, v);
    }
    __syncthreads();

    u64 acc[8][2];
    #pragma unroll
    for (int bb = 0; bb < 8; bb++){ acc[bb][0]=0ull; acc[bb][1]=0ull; }

    const float* wbase = W1 + ((size_t)s*D_ + dz*384)*F_ + f0;
    #pragma unroll 4
    for (int d0 = 0; d0 < 384; d0 += 2){
        const float* wp = wbase + (size_t)d0 * F_;
        ulonglong2 w0 = *(const ulonglong2*)(wp);
        ulonglong2 w1 = *(const ulonglong2*)(wp + F_);
        #pragma unroll
        for (int bb = 0; bb < 8; bb++){
            ulonglong2 yp = *(const ulonglong2*)&ys2[bb][d0];
            acc[bb][0]=ffma2(w0.x, yp.x, acc[bb][0]);
            acc[bb][1]=ffma2(w0.y, yp.x, acc[bb][1]);
            acc[bb][0]=ffma2(w1.x, yp.y, acc[bb][0]);
            acc[bb][1]=ffma2(w1.y, yp.y, acc[bb][1]);
        }
    }
    #pragma unroll
    for (int bb = 0; bb < 8; bb++){
        float* dst = &g_h[(size_t)(bb*S_ + s)*F_ + f0];
        float2 p0 = unpack2(acc[bb][0]);
        float2 p1 = unpack2(acc[bb][1]);
        atomicAdd(dst+0, p0.x);
        atomicAdd(dst+1, p0.y);
        atomicAdd(dst+2, p1.x);
        atomicAdd(dst+3, p1.y);
    }
}

// K8: y2 += sum_{f chunk} gelu(h_pre+b1)*W2  (splitF=8, atomics). 192 thr, 4 d per thread.
__global__ __launch_bounds__(192) void k_ffn2(const float* __restrict__ W2,
                                              const float* __restrict__ b1){
    int s  = blockIdx.x;
    int fz = blockIdx.y;
    int d0 = threadIdx.x * 4;
    __shared__ __align__(16) u64 hs2[8][384];
    #pragma unroll
    for (int it = 0; it < 16; it++){
        int i = it*192 + threadIdx.x;      // 0..3071
        int bb = i / 384, f = i - bb*384;
        float v = g_h[(size_t)(bb*S_ + s)*F_ + fz*384 + f];
        v = gelu_f(v + b1[s*F_ + fz*384 + f]);
        hs2[bb][f] = pack2(v, v);
    }
    __syncthreads();

    u64 acc[8][2];
    #pragma unroll
    for (int bb = 0; bb < 8; bb++){ acc[bb][0]=0ull; acc[bb][1]=0ull; }

    const float* wbase = W2 + ((size_t)s*F_ + fz*384)*D_ + d0;
    #pragma unroll 4
    for (int f0 = 0; f0 < 384; f0 += 2){
        const float* wp = wbase + (size_t)f0 * D_;
        ulonglong2 w0 = *(const ulonglong2*)(wp);
        ulonglong2 w1 = *(const ulonglong2*)(wp + D_);
        #pragma unroll
        for (int bb = 0; bb < 8; bb++){
            ulonglong2 hp = *(const ulonglong2*)&hs2[bb][f0];
            acc[bb][0]=ffma2(w0.x, hp.x, acc[bb][0]);
            acc[bb][1]=ffma2(w0.y, hp.x, acc[bb][1]);
            acc[bb][0]=ffma2(w1.x, hp.y, acc[bb][0]);
            acc[bb][1]=ffma2(w1.y, hp.y, acc[bb][1]);
        }
    }
    #pragma unroll
    for (int bb = 0; bb < 8; bb++){
        float* dst = &g_y2[(size_t)(bb*S_ + s)*D_ + d0];
        float2 p0 = unpack2(acc[bb][0]);
        float2 p1 = unpack2(acc[bb][1]);
        atomicAdd(dst+0, p0.x);
        atomicAdd(dst+1, p0.y);
        atomicAdd(dst+2, p1.x);
        atomicAdd(dst+3, p1.y);
    }
}

// K9: out[b][t][d] = sum_s (y2+b2)*comb. 64t x 128d, 256 thr, 8t x 4d per thread.
#define FINAL_SMEM (64*72*4 + 64*136*4)
__global__ __launch_bounds__(256) void k_final(const float* __restrict__ b2,
                                               float* __restrict__ out){
    extern __shared__ __align__(16) char smraw[];
    float* Cs = (float*)smraw;                 // [64][72]   comb [s][t]
    float* Ys = (float*)(smraw + 64*72*4);     // [64][136]  y2+bias [s][d]
    int t0 = blockIdx.x * 64;
    int dt = blockIdx.y * 128;
    int b  = blockIdx.z;
    int tid = threadIdx.x;
    int tg = tid >> 5;    // 8 t-groups of 8
    int dg = tid & 31;    // 32 d-groups of 4

    #pragma unroll
    for (int it = 0; it < 8; it++){
        int i = it*256 + tid;              // 0..2047
        int s = i >> 5, dq = (i & 31) << 2;
        float4 yv = *(const float4*)&g_y2[(size_t)(b*S_ + s)*D_ + dt + dq];
        float4 bv = *(const float4*)&b2[s*D_ + dt + dq];
        yv.x += bv.x; yv.y += bv.y; yv.z += bv.z; yv.w += bv.w;
        *(float4*)&Ys[s*136 + dq] = yv;
    }
    #pragma unroll
    for (int it = 0; it < 4; it++){
        int i = it*256 + tid;              // 0..1023
        int s = i >> 4, tq = (i & 15) << 2;
        *(float4*)&Cs[s*72 + tq] = *(const float4*)&g_comb[(size_t)(b*S_ + s)*T_ + t0 + tq];
    }
    __syncthreads();

    u64 acc[8][2];
    #pragma unroll
    for (int i = 0; i < 8; i++){ acc[i][0]=0ull; acc[i][1]=0ull; }

    #pragma unroll 4
    for (int s = 0; s < S_; s++){
        float4 c0 = *(const float4*)&Cs[s*72 + tg*8];
        float4 c1 = *(const float4*)&Cs[s*72 + tg*8 + 4];
        ulonglong2 ya = *(const ulonglong2*)&Ys[s*136 + dg*4];
        u64 cc[8];
        cc[0]=pack2(c0.x,c0.x); cc[1]=pack2(c0.y,c0.y); cc[2]=pack2(c0.z,c0.z); cc[3]=pack2(c0.w,c0.w);
        cc[4]=pack2(c1.x,c1.x); cc[5]=pack2(c1.y,c1.y); cc[6]=pack2(c1.z,c1.z); cc[7]=pack2(c1.w,c1.w);
        #pragma unroll
        for (int ti = 0; ti < 8; ti++){
            acc[ti][0]=ffma2(ya.x, cc[ti], acc[ti][0]);
            acc[ti][1]=ffma2(ya.y, cc[ti], acc[ti][1]);
        }
    }

    #pragma unroll
    for (int ti = 0; ti < 8; ti++){
        int t = t0 + tg*8 + ti;
        float2 p0 = unpack2(acc[ti][0]);
        float2 p1 = unpack2(acc[ti][1]);
        *(float4*)(out + (size_t)(b*T_ + t)*D_ + dt + dg*4) =
            make_float4(p0.x, p0.y, p1.x, p1.y);
    }
}

// -------- launch --------
extern "C" void kernel_launch(void* const* d_in, const int* in_sizes, int n_in,
                              void* d_out, int out_size){
    const float* x     = (const float*)d_in[0];
    const float* slots = (const float*)d_in[1];
    const float* scale = (const float*)d_in[2];
    const float* fc1_w = (const float*)d_in[3];
    const float* fc1_b = (const float*)d_in[4];
    const float* fc2_w = (const float*)d_in[5];
    const float* fc2_b = (const float*)d_in[6];
    const float* nw    = (const float*)d_in[7];
    float* out = (float*)d_out;

    cudaFuncSetAttribute(k_final, cudaFuncAttributeMaxDynamicSharedMemorySize, FINAL_SMEM);

    k_zero<<<1536, 256>>>();
    k_slot_prep<<<S_, 256>>>(slots, scale);
    k_rms<<<B_*T_, 256>>>(x, nw);
    k_logits<<<dim3(T_/128, B_, 2), 256>>>();
    k_disp_soft<<<dim3(S_, B_), 256>>>();
    k_comb_soft<<<dim3(T_/128, B_), 128>>>();
    k_dispatch<<<dim3(D_/128, B_, 8), 256>>>();
    k_ffn1a<<<dim3(F_/1024, S_, 2), 256>>>(fc1_w);
    k_ffn2<<<dim3(S_, 8), 192>>>(fc2_w, fc1_b);
    k_final<<<dim3(T_/64, D_/128, B_), 256, FINAL_SMEM>>>(fc2_b, out);
}